// round 7
// baseline (speedup 1.0000x reference)
#include <cuda_runtime.h>

// N-step discounted return, T=1024, B=4096, horizon=16, gamma=0.99.
// g[t,b] = sum_{h=0..15, t+h<T} g^h * r[t+h,b]*m[t+h,b]
//        + g^{min(t+16,T)-t} * V[min(t+15,T-1), b]
//
// Fully-vectorized smem time-tile:
//  - block = 256 threads, tile = 32 cols x 128 output rows
//  - phase 1: float4 cooperative loads, rm = rew*mask -> 18KB smem (144 rows)
//  - phase 2: thread = (col4, 4-row chunk); float4 backward sliding recurrence
//             S(t) = rm[t] + g*S(t+1) - g^16*rm[t+16]; float4 val/out.

#define TT 1024
#define BB 4096
#define HORIZON 16
#define BCOL 32                     // columns per block
#define TROWS 128                   // output rows per block
#define WROWS 144                   // staged rows (need 143)

constexpr float GAMMA = 0.99f;

__host__ __device__ constexpr float gpow(int n) {
    float x = 1.0f;
    for (int i = 0; i < n; ++i) x *= GAMMA;
    return x;
}

__device__ __constant__ float GP[17] = {
    gpow(0),  gpow(1),  gpow(2),  gpow(3),  gpow(4),  gpow(5),
    gpow(6),  gpow(7),  gpow(8),  gpow(9),  gpow(10), gpow(11),
    gpow(12), gpow(13), gpow(14), gpow(15), gpow(16)
};

__device__ __forceinline__ float4 f4_fma_s(float4 a, float s, float4 b) {
    // a*s + b, per component
    return make_float4(fmaf(a.x, s, b.x), fmaf(a.y, s, b.y),
                       fmaf(a.z, s, b.z), fmaf(a.w, s, b.w));
}

__global__ __launch_bounds__(256)
void nstep_return_kernel(const float* __restrict__ rew,
                         const float* __restrict__ val,
                         const float* __restrict__ msk,
                         float* __restrict__ out)
{
    __shared__ float rm[WROWS][BCOL];   // 144*32*4 = 18432 B

    const int tid   = threadIdx.x;
    const int bcol0 = blockIdx.x * BCOL;    // first column of this block
    const int t0    = blockIdx.y * TROWS;   // first output row of this block

    constexpr float G16 = gpow(16);

    // ---- Phase 1: stage rm = rew*mask for rows [t0, t0+WROWS) ----
    // 144 rows x 8 float4 = 1152 slots, 256 threads -> <=5 iters.
    for (int i = tid; i < WROWS * (BCOL / 4); i += 256) {
        const int r  = i >> 3;              // row in tile
        const int c4 = i & 7;               // float4 index in row
        const int tt = t0 + r;

        float4 p = make_float4(0.f, 0.f, 0.f, 0.f);
        if (tt < TT) {
            const size_t off = (size_t)tt * BB + bcol0 + c4 * 4;
            const float4 rv = *reinterpret_cast<const float4*>(rew + off);
            const float4 mv = *reinterpret_cast<const float4*>(msk + off);
            p = make_float4(rv.x * mv.x, rv.y * mv.y, rv.z * mv.z, rv.w * mv.w);
        }
        *reinterpret_cast<float4*>(&rm[r][c4 * 4]) = p;
    }
    __syncthreads();

    // ---- Phase 2: float4 sliding-window recurrence ----
    const int col4  = tid & 7;              // 0..7  -> cols [col4*4, col4*4+3]
    const int chunk = tid >> 3;             // 0..31 -> 4 rows each
    const int tl0   = chunk * 4;            // local row base
    const int c     = bcol0 + col4 * 4;     // global column of .x

    // S at local row tl0+3: Horner over rm rows [tl0+3 .. tl0+18].
    float4 S = make_float4(0.f, 0.f, 0.f, 0.f);
#pragma unroll
    for (int i = 18; i >= 3; --i) {
        const float4 x = *reinterpret_cast<const float4*>(&rm[tl0 + i][col4 * 4]);
        S = f4_fma_s(S, GAMMA, x);
    }

#pragma unroll
    for (int j = 3; j >= 0; --j) {
        const int t = t0 + tl0 + j;

        float4 v;
        float gb;
        if (t + HORIZON <= TT) {
            v  = *reinterpret_cast<const float4*>(val + (size_t)(t + HORIZON - 1) * BB + c);
            gb = G16;
        } else {
            v  = *reinterpret_cast<const float4*>(val + (size_t)(TT - 1) * BB + c);
            gb = GP[TT - t];
        }
        float4 o = make_float4(fmaf(gb, v.x, S.x), fmaf(gb, v.y, S.y),
                               fmaf(gb, v.z, S.z), fmaf(gb, v.w, S.w));
        *reinterpret_cast<float4*>(out + (size_t)t * BB + c) = o;

        if (j > 0) {
            const float4 lo = *reinterpret_cast<const float4*>(&rm[tl0 + j - 1][col4 * 4]);
            const float4 hi = *reinterpret_cast<const float4*>(&rm[tl0 + j + 15][col4 * 4]);
            // S = lo + g*S - g16*hi
            S = f4_fma_s(S, GAMMA, lo);
            S = make_float4(fmaf(-G16, hi.x, S.x), fmaf(-G16, hi.y, S.y),
                            fmaf(-G16, hi.z, S.z), fmaf(-G16, hi.w, S.w));
        }
    }
}

extern "C" void kernel_launch(void* const* d_in, const int* in_sizes, int n_in,
                              void* d_out, int out_size)
{
    const float* rewards = (const float*)d_in[0];
    const float* values  = (const float*)d_in[1];
    const float* masks   = (const float*)d_in[2];
    float*       out     = (float*)d_out;

    dim3 block(256);
    dim3 grid(BB / BCOL, TT / TROWS);   // (128, 8) = 1024 blocks
    nstep_return_kernel<<<grid, block>>>(rewards, values, masks, out);
}

// round 8
// speedup vs baseline: 1.0201x; 1.0201x over previous
#include <cuda_runtime.h>

// N-step discounted return, T=1024, B=4096, horizon=16, gamma=0.99.
// g[t,b] = sum_{h=0..15, t+h<T} g^h * r[t+h,b]*m[t+h,b]
//        + g^{min(t+16,T)-t} * V[min(t+15,T-1), b]
//
// Tile: 64 cols x 64 output rows per 256-thread block.
//  - entry:   each thread PREFETCHES its 4 bootstrap-value float4 rows into
//             registers (overlaps the staging loads + barrier)
//  - phase 1: cooperative float4 loads, rm = rew*mask -> 20KB smem (80 rows,
//             exactly 5 iterations per thread, fully unrolled)
//  - phase 2: thread = (col4 0..15, 4-row chunk 0..15); float4 backward
//             sliding recurrence S(t) = rm[t] + g*S(t+1) - g^16*rm[t+16];
//             zero GMEM loads (val already in regs), float4 stores.

#define TT 1024
#define BB 4096
#define HORIZON 16
#define BCOL 64                     // columns per block
#define TROWS 64                    // output rows per block
#define WROWS 80                    // staged rows (need 79; 80 = even split)

constexpr float GAMMA = 0.99f;

__host__ __device__ constexpr float gpow(int n) {
    float x = 1.0f;
    for (int i = 0; i < n; ++i) x *= GAMMA;
    return x;
}

__device__ __constant__ float GP[17] = {
    gpow(0),  gpow(1),  gpow(2),  gpow(3),  gpow(4),  gpow(5),
    gpow(6),  gpow(7),  gpow(8),  gpow(9),  gpow(10), gpow(11),
    gpow(12), gpow(13), gpow(14), gpow(15), gpow(16)
};

__device__ __forceinline__ float4 f4_fma_s(float4 a, float s, float4 b) {
    return make_float4(fmaf(a.x, s, b.x), fmaf(a.y, s, b.y),
                       fmaf(a.z, s, b.z), fmaf(a.w, s, b.w));
}

__global__ __launch_bounds__(256)
void nstep_return_kernel(const float* __restrict__ rew,
                         const float* __restrict__ val,
                         const float* __restrict__ msk,
                         float* __restrict__ out)
{
    __shared__ float rm[WROWS][BCOL];   // 80*64*4 = 20480 B

    const int tid   = threadIdx.x;
    const int bcol0 = blockIdx.x * BCOL;    // first column of this block
    const int t0    = blockIdx.y * TROWS;   // first output row of this block

    constexpr float G16 = gpow(16);

    // Phase-2 thread mapping (computed up front for the val prefetch).
    const int col4  = tid & 15;             // 0..15 -> cols [col4*4 .. col4*4+3]
    const int chunk = tid >> 4;             // 0..15 -> 4 output rows each
    const int tl0   = chunk * 4;            // local row base
    const int c     = bcol0 + col4 * 4;     // global column of .x
    const int trow  = t0 + tl0;             // thread's first output row

    // ---- Entry: prefetch bootstrap values (in flight across phase 1 + bar) ----
    float4 vpre[4];
#pragma unroll
    for (int j = 0; j < 4; ++j) {
        const int vr = min(trow + j + HORIZON - 1, TT - 1);
        vpre[j] = *reinterpret_cast<const float4*>(val + (size_t)vr * BB + c);
    }

    // ---- Phase 1: stage rm = rew*mask for rows [t0, t0+WROWS) ----
    // 80 rows x 16 float4 = 1280 slots = exactly 5 iterations of 256 threads.
#pragma unroll
    for (int it = 0; it < (WROWS * (BCOL / 4)) / 256; ++it) {
        const int i  = it * 256 + tid;
        const int r  = i >> 4;              // row in tile
        const int c4 = i & 15;              // float4 index in row
        const int tt = t0 + r;

        float4 p = make_float4(0.f, 0.f, 0.f, 0.f);
        if (tt < TT) {
            const size_t off = (size_t)tt * BB + bcol0 + c4 * 4;
            const float4 rv = *reinterpret_cast<const float4*>(rew + off);
            const float4 mv = *reinterpret_cast<const float4*>(msk + off);
            p = make_float4(rv.x * mv.x, rv.y * mv.y, rv.z * mv.z, rv.w * mv.w);
        }
        *reinterpret_cast<float4*>(&rm[r][c4 * 4]) = p;
    }
    __syncthreads();

    // ---- Phase 2: float4 sliding-window recurrence (smem + regs only) ----
    // S at local row tl0+3: Horner over rm rows [tl0+3 .. tl0+18].
    float4 S = make_float4(0.f, 0.f, 0.f, 0.f);
#pragma unroll
    for (int i = 18; i >= 3; --i) {
        const float4 x = *reinterpret_cast<const float4*>(&rm[tl0 + i][col4 * 4]);
        S = f4_fma_s(S, GAMMA, x);
    }

#pragma unroll
    for (int j = 3; j >= 0; --j) {
        const int t = trow + j;

        const float gb = (t + HORIZON <= TT) ? G16 : GP[TT - t];
        const float4 v = vpre[j];
        float4 o = make_float4(fmaf(gb, v.x, S.x), fmaf(gb, v.y, S.y),
                               fmaf(gb, v.z, S.z), fmaf(gb, v.w, S.w));
        *reinterpret_cast<float4*>(out + (size_t)t * BB + c) = o;

        if (j > 0) {
            const float4 lo = *reinterpret_cast<const float4*>(&rm[tl0 + j - 1][col4 * 4]);
            const float4 hi = *reinterpret_cast<const float4*>(&rm[tl0 + j + 15][col4 * 4]);
            S = f4_fma_s(S, GAMMA, lo);                      // g*S + rm[t-1]
            S = make_float4(fmaf(-G16, hi.x, S.x), fmaf(-G16, hi.y, S.y),
                            fmaf(-G16, hi.z, S.z), fmaf(-G16, hi.w, S.w));
        }
    }
}

extern "C" void kernel_launch(void* const* d_in, const int* in_sizes, int n_in,
                              void* d_out, int out_size)
{
    const float* rewards = (const float*)d_in[0];
    const float* values  = (const float*)d_in[1];
    const float* masks   = (const float*)d_in[2];
    float*       out     = (float*)d_out;

    dim3 block(256);
    dim3 grid(BB / BCOL, TT / TROWS);   // (64, 16) = 1024 blocks
    nstep_return_kernel<<<grid, block>>>(rewards, values, masks, out);
}